// round 16
// baseline (speedup 1.0000x reference)
#include <cuda_runtime.h>
#include <cuda_fp16.h>
#include <cstdint>

#define DIMV 768
#define NHEAD 16
#define PH 48
#define BATCH 4
#define TSEQ 2048
#define MTOT (BATCH * TSEQ)   // 8192
#define NQKV (3 * DIMV)       // 2304
#define SCALE 0.14433756729740643f   // 1/sqrt(48)

// Scratch (allocation-free rule: __device__ globals)
__device__ uint32_t g_Xh[MTOT * DIMV / 2];       // x rounded fp16 (packed pairs)
__device__ uint32_t g_WinTh[NQKV * DIMV / 2];    // w_in^T rounded fp16
__device__ uint32_t g_WoutTh[DIMV * DIMV / 2];   // w_out^T rounded fp16
__device__ uint32_t g_AttH[MTOT * DIMV / 2];     // attn out rounded fp16
__device__ __half g_Qh[MTOT * DIMV];             // q*scale rounded
__device__ __half g_Kh[MTOT * DIMV];             // k rounded
__device__ __half g_Vth[64 * PH * TSEQ];         // v transposed rounded [bh][d][t]

// ---- fp16 helpers ----
__device__ __forceinline__ uint32_t pkh2(float lo, float hi) {
    uint32_t r;
    asm("cvt.rn.f16x2.f32 %0, %1, %2;" : "=r"(r) : "f"(hi), "f"(lo));
    return r;
}

// ---- fp16 m16n8k16 mma, fp32 accum ----
__device__ __forceinline__ void mma16816h(float* c, uint32_t a0, uint32_t a1,
                                          uint32_t a2, uint32_t a3,
                                          uint32_t b0, uint32_t b1) {
    asm volatile(
        "mma.sync.aligned.m16n8k16.row.col.f32.f16.f16.f32 "
        "{%0,%1,%2,%3},{%4,%5,%6,%7},{%8,%9},{%0,%1,%2,%3};"
        : "+f"(c[0]), "+f"(c[1]), "+f"(c[2]), "+f"(c[3])
        : "r"(a0), "r"(a1), "r"(a2), "r"(a3), "r"(b0), "r"(b1));
}

// ---- cp.async ----
__device__ __forceinline__ void cpa16(uint32_t dst_smem, const void* src) {
    asm volatile("cp.async.cg.shared.global [%0], [%1], 16;"
                 :: "r"(dst_smem), "l"(src));
}
__device__ __forceinline__ void cpa_commit() {
    asm volatile("cp.async.commit_group;");
}
__device__ __forceinline__ void cpa_wait1() {
    asm volatile("cp.async.wait_group 1;");
}
__device__ __forceinline__ void cpa_wait0() {
    asm volatile("cp.async.wait_group 0;");
}
__device__ __forceinline__ uint32_t smem_u32(const void* p) {
    return (uint32_t)__cvta_generic_to_shared(p);
}

// ---------------------------------------------------------------------------
// x -> rounded fp16 pairs
// ---------------------------------------------------------------------------
__global__ void __launch_bounds__(256) convert_x_kernel(const float* __restrict__ x)
{
    const long i = (long)blockIdx.x * 256 + threadIdx.x;
    float2 v = ((const float2*)x)[i];
    g_Xh[i] = pkh2(v.x, v.y);
}

// ---------------------------------------------------------------------------
// Transpose + ROUND weights: W[K][N] fp32 -> Wt[N][K] fp16 pairs
// ---------------------------------------------------------------------------
__global__ void __launch_bounds__(256) convert_w_kernel(
    const float* __restrict__ W, uint32_t* __restrict__ WtH, int K, int N)
{
    __shared__ float sT[32][33];
    const int k0 = blockIdx.y * 32, n0 = blockIdx.x * 32;
    const int tid = threadIdx.x;
    const int tx = tid & 31, ty = tid >> 5;
    #pragma unroll
    for (int i = 0; i < 4; i++)
        sT[ty + i * 8][tx] = W[(long)(k0 + ty + i * 8) * N + n0 + tx];
    __syncthreads();

    const int nr = tid >> 3;
    const int kc = tid & 7;
    #pragma unroll
    for (int i = 0; i < 2; i++) {
        int kk = kc + i * 8;
        long o = (long)(n0 + nr) * (K / 2) + k0 / 2 + kk;
        WtH[o] = pkh2(sT[2 * kk][nr], sT[2 * kk + 1][nr]);
    }
}

// ===========================================================================
// GEMM kernels: BK=32, 3-stage cp.async pipeline, ONE sync per iteration.
// ===========================================================================
#define G_STG_A 5120                        // halves per A stage (128*40)
#define G_STG_B 5120                        // halves per B stage (128*40)
#define G_SMEM ((3 * (G_STG_A + G_STG_B)) * 2)   // 61440 bytes

// ---------------------------------------------------------------------------
// QKV GEMM with FUSED epilogue (BM=BN=128).
// ---------------------------------------------------------------------------
__global__ void __launch_bounds__(256, 2) gemm_qkv_fused_kernel(
    const uint4* __restrict__ A, const uint4* __restrict__ B,
    const float* __restrict__ bias)
{
    const int K = DIMV;
    extern __shared__ __align__(16) __half dynG[];
    __half* sAb = dynG;                    // 3 stages x 128 x 40
    __half* sBb = dynG + 3 * G_STG_A;

    const int tid = threadIdx.x;
    const int wid = tid >> 5;
    const int lane = tid & 31;
    const int g = lane >> 2;
    const int t4 = lane & 3;
    const int wr = wid >> 2;
    const int wc = wid & 3;

    const int m0 = blockIdx.y * 128;
    const int n0 = blockIdx.x * 128;
    const int row = tid >> 1;
    const int half = tid & 1;
    const int Ku4 = K >> 3;

    const uint4* pA = A + (long)(m0 + row) * Ku4 + half * 2;
    const uint4* pB = B + (long)(n0 + row) * Ku4 + half * 2;

    const uint32_t dA0 = smem_u32(sAb + row * 40 + half * 16);
    const uint32_t dB0 = smem_u32(sBb + row * 40 + half * 16);
    const uint32_t stgA = G_STG_A * 2, stgB = G_STG_B * 2;   // bytes

    float acc[4][4][4];
    #pragma unroll
    for (int mt = 0; mt < 4; mt++)
        #pragma unroll
        for (int nt = 0; nt < 4; nt++)
            #pragma unroll
            for (int j = 0; j < 4; j++) acc[mt][nt][j] = 0.f;

    const int NIT = K / 32;   // 24
    // prologue: stages 0,1
    #pragma unroll
    for (int p = 0; p < 2; p++) {
        cpa16(dA0 + p * stgA, pA + p * 4);
        cpa16(dA0 + p * stgA + 16, pA + p * 4 + 1);
        cpa16(dB0 + p * stgB, pB + p * 4);
        cpa16(dB0 + p * stgB + 16, pB + p * 4 + 1);
        cpa_commit();
    }

    for (int it = 0; it < NIT; it++) {
        if (it + 1 < NIT) cpa_wait1(); else cpa_wait0();
        __syncthreads();
        if (it + 2 < NIT) {
            int s = (it + 2) % 3;
            const uint4* nA = pA + (it + 2) * 4;
            const uint4* nB = pB + (it + 2) * 4;
            cpa16(dA0 + s * stgA, nA);      cpa16(dA0 + s * stgA + 16, nA + 1);
            cpa16(dB0 + s * stgB, nB);      cpa16(dB0 + s * stgB + 16, nB + 1);
            cpa_commit();
        }

        const int st = it % 3;
        const uint32_t* sA0 = (const uint32_t*)(sAb + st * G_STG_A);
        const uint32_t* sB0 = (const uint32_t*)(sBb + st * G_STG_B);

        #pragma unroll
        for (int kk = 0; kk < 2; kk++) {
            const int ko = kk * 8;
            uint32_t bf[4][2];
            #pragma unroll
            for (int nt = 0; nt < 4; nt++) {
                int n = wc * 32 + nt * 8 + g;
                bf[nt][0] = sB0[n * 20 + ko + t4];
                bf[nt][1] = sB0[n * 20 + ko + t4 + 4];
            }
            uint32_t af[4][4];
            #pragma unroll
            for (int mt = 0; mt < 4; mt++) {
                int r0 = (wr * 64 + mt * 16 + g) * 20 + ko;
                int r1 = r0 + 8 * 20;
                af[mt][0] = sA0[r0 + t4];     af[mt][1] = sA0[r1 + t4];
                af[mt][2] = sA0[r0 + t4 + 4]; af[mt][3] = sA0[r1 + t4 + 4];
            }
            #pragma unroll
            for (int mt = 0; mt < 4; mt++)
                #pragma unroll
                for (int nt = 0; nt < 4; nt++)
                    mma16816h(acc[mt][nt], af[mt][0], af[mt][1], af[mt][2], af[mt][3],
                              bf[nt][0], bf[nt][1]);
        }
    }

    // Fused epilogue: route each column pair to Q / K / V-transposed fp16.
    uint32_t* Qh32 = (uint32_t*)g_Qh;
    uint32_t* Kh32 = (uint32_t*)g_Kh;
    #pragma unroll
    for (int mt = 0; mt < 4; mt++) {
        const int r = m0 + wr * 64 + mt * 16 + g;
        #pragma unroll
        for (int nt = 0; nt < 4; nt++) {
            const int c = n0 + wc * 32 + nt * 8 + 2 * t4;
            const float b0 = bias[c], b1 = bias[c + 1];
            const int h  = c / 144;
            const int rr = c - h * 144;
            float v00 = acc[mt][nt][0] + b0, v01 = acc[mt][nt][1] + b1;
            float v10 = acc[mt][nt][2] + b0, v11 = acc[mt][nt][3] + b1;
            if (rr < 48) {
                Qh32[((long)r * DIMV + h * PH + rr) >> 1] =
                    pkh2(v00 * SCALE, v01 * SCALE);
                Qh32[((long)(r + 8) * DIMV + h * PH + rr) >> 1] =
                    pkh2(v10 * SCALE, v11 * SCALE);
            } else if (rr < 96) {
                const int d = rr - 48;
                Kh32[((long)r * DIMV + h * PH + d) >> 1] = pkh2(v00, v01);
                Kh32[((long)(r + 8) * DIMV + h * PH + d) >> 1] = pkh2(v10, v11);
            } else {
                const int d = rr - 96;
                const int bb = r >> 11;
                const int t  = r & 2047;
                const long vb = ((long)(bb * NHEAD + h) * PH + d) * TSEQ + t;
                g_Vth[vb]            = __float2half_rn(v00);
                g_Vth[vb + TSEQ]     = __float2half_rn(v01);
                g_Vth[vb + 8]        = __float2half_rn(v10);
                g_Vth[vb + TSEQ + 8] = __float2half_rn(v11);
            }
        }
    }
}

// ---------------------------------------------------------------------------
// Output projection GEMM: BM=64, BN=128 (768 CTAs -> better wave balance).
// 8 warps as 2(m) x 4(n); warp tile 32x32.
// ---------------------------------------------------------------------------
#define O_STG_A 2560                       // halves per A stage (64*40)
#define O_STG_B 5120                       // halves per B stage (128*40)
#define O_SMEM ((3 * (O_STG_A + O_STG_B)) * 2)   // 46080 bytes

__global__ void __launch_bounds__(256, 2) gemm_out_kernel(
    const uint4* __restrict__ A, const uint4* __restrict__ B,
    const float* __restrict__ bias, float* __restrict__ C)
{
    const int N = DIMV, K = DIMV;
    extern __shared__ __align__(16) __half dynO[];
    __half* sAb = dynO;                    // 3 stages x 64 x 40
    __half* sBb = dynO + 3 * O_STG_A;      // 3 stages x 128 x 40

    const int tid = threadIdx.x;
    const int wid = tid >> 5;
    const int lane = tid & 31;
    const int g = lane >> 2;
    const int t4 = lane & 3;
    const int wr = wid >> 2;               // 0..1 -> m offset wr*32
    const int wc = wid & 3;                // 0..3 -> n offset wc*32

    const int m0 = blockIdx.y * 64;
    const int n0 = blockIdx.x * 128;
    const int Ku4 = K >> 3;                // 96

    // A loads: 64 rows x 4 uint4 = 256 -> 1 per thread
    const int arow = tid >> 2, aqc = tid & 3;
    const uint4* pA = A + (long)(m0 + arow) * Ku4 + aqc;
    const uint32_t dA0 = smem_u32(sAb + arow * 40 + aqc * 8);
    // B loads: 128 rows x 4 uint4 = 512 -> 2 per thread
    const int brow0 = tid >> 2, bqc = tid & 3;     // idx = tid
    const int brow1 = (tid + 256) >> 2;            // idx = tid + 256
    const uint4* pB0 = B + (long)(n0 + brow0) * Ku4 + bqc;
    const uint4* pB1 = B + (long)(n0 + brow1) * Ku4 + bqc;
    const uint32_t dB0 = smem_u32(sBb + brow0 * 40 + bqc * 8);
    const uint32_t dB1 = smem_u32(sBb + brow1 * 40 + bqc * 8);
    const uint32_t stgA = O_STG_A * 2, stgB = O_STG_B * 2;

    float acc[2][4][4];
    #pragma unroll
    for (int mt = 0; mt < 2; mt++)
        #pragma unroll
        for (int nt = 0; nt < 4; nt++)
            #pragma unroll
            for (int j = 0; j < 4; j++) acc[mt][nt][j] = 0.f;

    const int NIT = K / 32;   // 24
    #pragma unroll
    for (int p = 0; p < 2; p++) {
        cpa16(dA0 + p * stgA, pA + p * 4);
        cpa16(dB0 + p * stgB, pB0 + p * 4);
        cpa16(dB1 + p * stgB, pB1 + p * 4);
        cpa_commit();
    }

    for (int it = 0; it < NIT; it++) {
        if (it + 1 < NIT) cpa_wait1(); else cpa_wait0();
        __syncthreads();
        if (it + 2 < NIT) {
            int s = (it + 2) % 3;
            cpa16(dA0 + s * stgA, pA + (it + 2) * 4);
            cpa16(dB0 + s * stgB, pB0 + (it + 2) * 4);
            cpa16(dB1 + s * stgB, pB1 + (it + 2) * 4);
            cpa_commit();
        }

        const int st = it % 3;
        const uint32_t* sA0 = (const uint32_t*)(sAb + st * O_STG_A);
        const uint32_t* sB0 = (const uint32_t*)(sBb + st * O_STG_B);

        #pragma unroll
        for (int kk = 0; kk < 2; kk++) {
            const int ko = kk * 8;
            uint32_t bf[4][2];
            #pragma unroll
            for (int nt = 0; nt < 4; nt++) {
                int n = wc * 32 + nt * 8 + g;
                bf[nt][0] = sB0[n * 20 + ko + t4];
                bf[nt][1] = sB0[n * 20 + ko + t4 + 4];
            }
            uint32_t af[2][4];
            #pragma unroll
            for (int mt = 0; mt < 2; mt++) {
                int r0 = (wr * 32 + mt * 16 + g) * 20 + ko;
                int r1 = r0 + 8 * 20;
                af[mt][0] = sA0[r0 + t4];     af[mt][1] = sA0[r1 + t4];
                af[mt][2] = sA0[r0 + t4 + 4]; af[mt][3] = sA0[r1 + t4 + 4];
            }
            #pragma unroll
            for (int mt = 0; mt < 2; mt++)
                #pragma unroll
                for (int nt = 0; nt < 4; nt++)
                    mma16816h(acc[mt][nt], af[mt][0], af[mt][1], af[mt][2], af[mt][3],
                              bf[nt][0], bf[nt][1]);
        }
    }

    #pragma unroll
    for (int mt = 0; mt < 2; mt++) {
        int r = m0 + wr * 32 + mt * 16 + g;
        #pragma unroll
        for (int nt = 0; nt < 4; nt++) {
            int c = n0 + wc * 32 + nt * 8 + 2 * t4;
            float b0 = bias[c], b1 = bias[c + 1];
            *(float2*)&C[(long)r * N + c] =
                make_float2(acc[mt][nt][0] + b0, acc[mt][nt][1] + b1);
            *(float2*)&C[(long)(r + 8) * N + c] =
                make_float2(acc[mt][nt][2] + b0, acc[mt][nt][3] + b1);
        }
    }
}

// ---------------------------------------------------------------------------
// Flash attention fp16: 3-stage pipeline, one sync per tile.
// ---------------------------------------------------------------------------
#define SK_ELEMS (64 * 56)                 // 3584
#define STAGE_ELEMS (SK_ELEMS + 48 * 72)   // 7040
#define ATTN_SMEM (3 * STAGE_ELEMS * 2)    // 42240 bytes

__global__ void __launch_bounds__(256, 2) attn_mma_kernel()
{
    extern __shared__ __align__(16) __half dyn[];

    const int tid = threadIdx.x;
    const int wid = tid >> 5;
    const int lane = tid & 31;
    const int g = lane >> 2;
    const int t4 = lane & 3;

    const int bh = blockIdx.y;
    const int b = bh >> 4;
    const int h = bh & 15;
    const int qr0 = blockIdx.x * 128 + wid * 16;
    const long rowg  = (long)b * TSEQ + qr0 + g;
    const long rowg8 = rowg + 8;

    auto load_tile = [&](int kb, int st) {
        __half* base = dyn + st * STAGE_ELEMS;
        #pragma unroll
        for (int i = 0; i < 3; i++) {
            int idx = tid + 256 * i;
            if (idx < 384) {                     // K: 64 rows x 6 chunks
                int key = idx / 6, c = idx - key * 6;
                const __half* src = g_Kh
                    + (long)(b * TSEQ + kb + key) * DIMV + h * PH + c * 8;
                cpa16(smem_u32(base + key * 56 + c * 8), src);
            } else {                             // V: 48 dims x 8 chunks
                int v = idx - 384;
                int d = v >> 3, c = v & 7;
                const __half* src = g_Vth
                    + (long)bh * (PH * TSEQ) + d * TSEQ + kb + c * 8;
                cpa16(smem_u32(base + SK_ELEMS + d * 72 + c * 8), src);
            }
        }
        cpa_commit();
    };

    const uint32_t* Qh32 = (const uint32_t*)g_Qh;
    uint32_t qh[3][4];
    #pragma unroll
    for (int kk = 0; kk < 3; kk++) {
        long o0 = rowg  * 384 + h * 24 + kk * 8 + t4;
        long o1 = rowg8 * 384 + h * 24 + kk * 8 + t4;
        qh[kk][0] = Qh32[o0];     qh[kk][1] = Qh32[o1];
        qh[kk][2] = Qh32[o0 + 4]; qh[kk][3] = Qh32[o1 + 4];
    }

    float O[6][4];
    #pragma unroll
    for (int i = 0; i < 6; i++)
        #pragma unroll
        for (int j = 0; j < 4; j++) O[i][j] = 0.f;
    float m0 = -1e30f, m1 = -1e30f, l0 = 0.f, l1 = 0.f;

    load_tile(0, 0);
    load_tile(64, 1);

    const int NT = TSEQ / 64;   // 32
    for (int t = 0; t < NT; t++) {
        if (t + 1 < NT) cpa_wait1(); else cpa_wait0();
        __syncthreads();
        if (t + 2 < NT) load_tile((t + 2) * 64, (t + 2) % 3);

        const int st = t % 3;
        const __half* sK0 = dyn + st * STAGE_ELEMS;
        const __half* sV0 = sK0 + SK_ELEMS;

        float S[8][4];
        #pragma unroll
        for (int n = 0; n < 8; n++)
            #pragma unroll
            for (int j = 0; j < 4; j++) S[n][j] = 0.f;

        #pragma unroll
        for (int kk = 0; kk < 3; kk++) {
            uint32_t kf[8][2];
            #pragma unroll
            for (int n = 0; n < 8; n++) {
                const uint32_t* kp = (const uint32_t*)(sK0 + (n * 8 + g) * 56 + kk * 16 + 2 * t4);
                kf[n][0] = kp[0]; kf[n][1] = kp[4];
            }
            #pragma unroll
            for (int n = 0; n < 8; n++)
                mma16816h(S[n], qh[kk][0], qh[kk][1], qh[kk][2], qh[kk][3], kf[n][0], kf[n][1]);
        }

        float rmax0 = -1e30f, rmax1 = -1e30f;
        #pragma unroll
        for (int n = 0; n < 8; n++) {
            rmax0 = fmaxf(rmax0, fmaxf(S[n][0], S[n][1]));
            rmax1 = fmaxf(rmax1, fmaxf(S[n][2], S[n][3]));
        }
        rmax0 = fmaxf(rmax0, __shfl_xor_sync(0xffffffffu, rmax0, 1));
        rmax0 = fmaxf(rmax0, __shfl_xor_sync(0xffffffffu, rmax0, 2));
        rmax1 = fmaxf(rmax1, __shfl_xor_sync(0xffffffffu, rmax1, 1));
        rmax1 = fmaxf(rmax1, __shfl_xor_sync(0xffffffffu, rmax1, 2));

        float mn0 = fmaxf(m0, rmax0);
        float mn1 = fmaxf(m1, rmax1);
        float corr0 = __expf(m0 - mn0);
        float corr1 = __expf(m1 - mn1);
        m0 = mn0; m1 = mn1;
        l0 *= corr0; l1 *= corr1;
        #pragma unroll
        for (int nd = 0; nd < 6; nd++) {
            O[nd][0] *= corr0; O[nd][1] *= corr0;
            O[nd][2] *= corr1; O[nd][3] *= corr1;
        }

        float ps0 = 0.f, ps1 = 0.f;
        #pragma unroll
        for (int n = 0; n < 8; n++) {
            S[n][0] = __expf(S[n][0] - m0);
            S[n][1] = __expf(S[n][1] - m0);
            S[n][2] = __expf(S[n][2] - m1);
            S[n][3] = __expf(S[n][3] - m1);
            ps0 += S[n][0] + S[n][1];
            ps1 += S[n][2] + S[n][3];
        }
        ps0 += __shfl_xor_sync(0xffffffffu, ps0, 1);
        ps0 += __shfl_xor_sync(0xffffffffu, ps0, 2);
        ps1 += __shfl_xor_sync(0xffffffffu, ps1, 1);
        ps1 += __shfl_xor_sync(0xffffffffu, ps1, 2);
        l0 += ps0; l1 += ps1;

        #pragma unroll
        for (int kk = 0; kk < 4; kk++) {
            uint32_t ph[4];
            #pragma unroll
            for (int half = 0; half < 2; half++) {
                const float* Sc = S[2 * kk + half];
                ph[2 * half + 0] = pkh2(Sc[0], Sc[1]);
                ph[2 * half + 1] = pkh2(Sc[2], Sc[3]);
            }
            uint32_t vf[6][2];
            #pragma unroll
            for (int nd = 0; nd < 6; nd++) {
                const uint32_t* vp = (const uint32_t*)(sV0 + (nd * 8 + g) * 72 + kk * 16 + 2 * t4);
                vf[nd][0] = vp[0]; vf[nd][1] = vp[4];
            }
            #pragma unroll
            for (int nd = 0; nd < 6; nd++)
                mma16816h(O[nd], ph[0], ph[1], ph[2], ph[3], vf[nd][0], vf[nd][1]);
        }
    }

    const float invl0 = 1.0f / l0;
    const float invl1 = 1.0f / l1;
    #pragma unroll
    for (int nd = 0; nd < 6; nd++) {
        long c = h * PH + nd * 8 + 2 * t4;
        g_AttH[(rowg  * DIMV + c) >> 1] =
            pkh2(O[nd][0] * invl0, O[nd][1] * invl0);
        g_AttH[(rowg8 * DIMV + c) >> 1] =
            pkh2(O[nd][2] * invl1, O[nd][3] * invl1);
    }
}

// ---------------------------------------------------------------------------
extern "C" void kernel_launch(void* const* d_in, const int* in_sizes, int n_in,
                              void* d_out, int out_size)
{
    const float* x     = (const float*)d_in[0];
    const float* w_in  = (const float*)d_in[1];
    const float* b_in  = (const float*)d_in[2];
    const float* w_out = (const float*)d_in[3];
    const float* b_out = (const float*)d_in[4];
    float* out = (float*)d_out;

    static bool attr_set = false;
    if (!attr_set) {
        cudaFuncSetAttribute(gemm_qkv_fused_kernel,
                             cudaFuncAttributeMaxDynamicSharedMemorySize, G_SMEM);
        cudaFuncSetAttribute(gemm_out_kernel,
                             cudaFuncAttributeMaxDynamicSharedMemorySize, O_SMEM);
        cudaFuncSetAttribute(attn_mma_kernel,
                             cudaFuncAttributeMaxDynamicSharedMemorySize, ATTN_SMEM);
        attr_set = true;
    }

    uint32_t *Xh, *WinTh, *WoutTh, *AttH;
    cudaGetSymbolAddress((void**)&Xh, g_Xh);
    cudaGetSymbolAddress((void**)&WinTh, g_WinTh);
    cudaGetSymbolAddress((void**)&WoutTh, g_WoutTh);
    cudaGetSymbolAddress((void**)&AttH, g_AttH);

    convert_x_kernel<<<(MTOT * DIMV / 2) / 256, 256>>>(x);
    {
        dim3 grid(NQKV / 32, DIMV / 32);
        convert_w_kernel<<<grid, 256>>>(w_in, WinTh, DIMV, NQKV);
    }
    {
        dim3 grid(DIMV / 32, DIMV / 32);
        convert_w_kernel<<<grid, 256>>>(w_out, WoutTh, DIMV, DIMV);
    }

    // QKV projection with fused fp16 Q/K/V-transpose epilogue
    {
        dim3 grid(NQKV / 128, MTOT / 128);
        gemm_qkv_fused_kernel<<<grid, 256, G_SMEM>>>((const uint4*)Xh,
                                                     (const uint4*)WinTh, b_in);
    }

    // Attention (QK x1, PV x1)
    {
        dim3 grid(TSEQ / 128, 64);
        attn_mma_kernel<<<grid, 256, ATTN_SMEM>>>();
    }

    // Output projection (BM=64 grid for wave balance) -> fp32 d_out
    {
        dim3 grid(DIMV / 128, MTOT / 64);
        gemm_out_kernel<<<grid, 256, O_SMEM>>>((const uint4*)AttH,
                                               (const uint4*)WoutTh, b_out, out);
    }
}

// round 17
// speedup vs baseline: 1.0349x; 1.0349x over previous
#include <cuda_runtime.h>
#include <cuda_fp16.h>
#include <cstdint>

#define DIMV 768
#define NHEAD 16
#define PH 48
#define BATCH 4
#define TSEQ 2048
#define MTOT (BATCH * TSEQ)   // 8192
#define NQKV (3 * DIMV)       // 2304
#define SCALE 0.14433756729740643f   // 1/sqrt(48)

// Scratch (allocation-free rule: __device__ globals)
__device__ uint32_t g_Xh[MTOT * DIMV / 2];       // x rounded fp16 (packed pairs)
__device__ uint32_t g_WinTh[NQKV * DIMV / 2];    // w_in^T rounded fp16
__device__ uint32_t g_WoutTh[DIMV * DIMV / 2];   // w_out^T rounded fp16
__device__ uint32_t g_AttH[MTOT * DIMV / 2];     // attn out rounded fp16
__device__ __half g_Qh[MTOT * DIMV];             // q*scale rounded
__device__ __half g_Kh[MTOT * DIMV];             // k rounded
__device__ __half g_Vth[64 * PH * TSEQ];         // v transposed rounded [bh][d][t]

// ---- fp16 helpers ----
__device__ __forceinline__ uint32_t pkh2(float lo, float hi) {
    uint32_t r;
    asm("cvt.rn.f16x2.f32 %0, %1, %2;" : "=r"(r) : "f"(hi), "f"(lo));
    return r;
}

// ---- fp16 m16n8k16 mma, fp32 accum ----
__device__ __forceinline__ void mma16816h(float* c, uint32_t a0, uint32_t a1,
                                          uint32_t a2, uint32_t a3,
                                          uint32_t b0, uint32_t b1) {
    asm volatile(
        "mma.sync.aligned.m16n8k16.row.col.f32.f16.f16.f32 "
        "{%0,%1,%2,%3},{%4,%5,%6,%7},{%8,%9},{%0,%1,%2,%3};"
        : "+f"(c[0]), "+f"(c[1]), "+f"(c[2]), "+f"(c[3])
        : "r"(a0), "r"(a1), "r"(a2), "r"(a3), "r"(b0), "r"(b1));
}

// ---- cp.async ----
__device__ __forceinline__ void cpa16(uint32_t dst_smem, const void* src) {
    asm volatile("cp.async.cg.shared.global [%0], [%1], 16;"
                 :: "r"(dst_smem), "l"(src));
}
__device__ __forceinline__ void cpa_commit() {
    asm volatile("cp.async.commit_group;");
}
__device__ __forceinline__ void cpa_wait1() {
    asm volatile("cp.async.wait_group 1;");
}
__device__ __forceinline__ void cpa_wait0() {
    asm volatile("cp.async.wait_group 0;");
}
__device__ __forceinline__ uint32_t smem_u32(const void* p) {
    return (uint32_t)__cvta_generic_to_shared(p);
}

// ---------------------------------------------------------------------------
// MERGED convert kernel: one launch handles x-rounding + both weight
// transposes, dispatched by blockIdx.x region.
//   blocks [0, XB)            : x -> fp16 pairs          (XB = MTOT*DIMV/2/256)
//   blocks [XB, XB+WIB)       : w_in transpose+round     (WIB = 72*24)
//   blocks [XB+WIB, +WOB)     : w_out transpose+round    (WOB = 24*24)
// ---------------------------------------------------------------------------
#define XB  (MTOT * DIMV / 2 / 256)     // 12288
#define WIB ((NQKV / 32) * (DIMV / 32)) // 1728
#define WOB ((DIMV / 32) * (DIMV / 32)) // 576

__global__ void __launch_bounds__(256) convert_all_kernel(
    const float* __restrict__ x,
    const float* __restrict__ w_in,
    const float* __restrict__ w_out)
{
    const int blk = blockIdx.x;
    const int tid = threadIdx.x;

    if (blk < XB) {
        const long i = (long)blk * 256 + tid;
        float2 v = ((const float2*)x)[i];
        g_Xh[i] = pkh2(v.x, v.y);
        return;
    }

    // weight transpose region
    __shared__ float sT[32][33];
    const float* W;
    uint32_t* WtH;
    int K, N, bx, by;
    if (blk < XB + WIB) {
        int wb = blk - XB;
        W = w_in; WtH = g_WinTh; K = DIMV; N = NQKV;
        bx = wb % (NQKV / 32); by = wb / (NQKV / 32);
    } else {
        int wb = blk - XB - WIB;
        W = w_out; WtH = g_WoutTh; K = DIMV; N = DIMV;
        bx = wb % (DIMV / 32); by = wb / (DIMV / 32);
    }
    const int k0 = by * 32, n0 = bx * 32;
    const int tx = tid & 31, ty = tid >> 5;
    #pragma unroll
    for (int i = 0; i < 4; i++)
        sT[ty + i * 8][tx] = W[(long)(k0 + ty + i * 8) * N + n0 + tx];
    __syncthreads();

    const int nr = tid >> 3;
    const int kc = tid & 7;
    #pragma unroll
    for (int i = 0; i < 2; i++) {
        int kk = kc + i * 8;
        long o = (long)(n0 + nr) * (K / 2) + k0 / 2 + kk;
        WtH[o] = pkh2(sT[2 * kk][nr], sT[2 * kk + 1][nr]);
    }
}

// ---------------------------------------------------------------------------
// QKV GEMM with FUSED epilogue (R15 config: BK=32, 2-stage, static smem).
// Writes g_Qh (scaled), g_Kh, g_Vth (transposed) as rounded fp16.
// ---------------------------------------------------------------------------
__global__ void __launch_bounds__(256, 2) gemm_qkv_fused_kernel(
    const uint4* __restrict__ A, const uint4* __restrict__ B,
    const float* __restrict__ bias)
{
    const int K = DIMV;
    __shared__ __align__(16) __half sA[2][128][40];
    __shared__ __align__(16) __half sB[2][128][40];

    const int tid = threadIdx.x;
    const int wid = tid >> 5;
    const int lane = tid & 31;
    const int g = lane >> 2;
    const int t4 = lane & 3;
    const int wr = wid >> 2;
    const int wc = wid & 3;

    const int m0 = blockIdx.y * 128;
    const int n0 = blockIdx.x * 128;
    const int row = tid >> 1;
    const int half = tid & 1;
    const int Ku4 = K >> 3;

    const uint4* pA = A + (long)(m0 + row) * Ku4 + half * 2;
    const uint4* pB = B + (long)(n0 + row) * Ku4 + half * 2;

    const uint32_t dA0 = smem_u32(&sA[0][row][half * 16]);
    const uint32_t dB0 = smem_u32(&sB[0][row][half * 16]);
    const uint32_t stg = 128 * 40 * 2;

    float acc[4][4][4];
    #pragma unroll
    for (int mt = 0; mt < 4; mt++)
        #pragma unroll
        for (int nt = 0; nt < 4; nt++)
            #pragma unroll
            for (int j = 0; j < 4; j++) acc[mt][nt][j] = 0.f;

    const int NIT = K / 32;
    cpa16(dA0, pA);      cpa16(dA0 + 16, pA + 1);
    cpa16(dB0, pB);      cpa16(dB0 + 16, pB + 1);
    cpa_commit();

    for (int it = 0; it < NIT; it++) {
        if (it + 1 < NIT) {
            uint32_t s = (it + 1) & 1;
            const uint4* nA = pA + (it + 1) * 4;
            const uint4* nB = pB + (it + 1) * 4;
            cpa16(dA0 + s * stg, nA);      cpa16(dA0 + s * stg + 16, nA + 1);
            cpa16(dB0 + s * stg, nB);      cpa16(dB0 + s * stg + 16, nB + 1);
            cpa_commit();
            cpa_wait1();
        } else {
            cpa_wait0();
        }
        __syncthreads();

        const int st = it & 1;
        const uint32_t* sA0 = (const uint32_t*)sA[st];
        const uint32_t* sB0 = (const uint32_t*)sB[st];

        #pragma unroll
        for (int kk = 0; kk < 2; kk++) {
            const int ko = kk * 8;
            uint32_t bf[4][2];
            #pragma unroll
            for (int nt = 0; nt < 4; nt++) {
                int n = wc * 32 + nt * 8 + g;
                bf[nt][0] = sB0[n * 20 + ko + t4];
                bf[nt][1] = sB0[n * 20 + ko + t4 + 4];
            }
            uint32_t af[4][4];
            #pragma unroll
            for (int mt = 0; mt < 4; mt++) {
                int r0 = (wr * 64 + mt * 16 + g) * 20 + ko;
                int r1 = r0 + 8 * 20;
                af[mt][0] = sA0[r0 + t4];     af[mt][1] = sA0[r1 + t4];
                af[mt][2] = sA0[r0 + t4 + 4]; af[mt][3] = sA0[r1 + t4 + 4];
            }
            #pragma unroll
            for (int mt = 0; mt < 4; mt++)
                #pragma unroll
                for (int nt = 0; nt < 4; nt++)
                    mma16816h(acc[mt][nt], af[mt][0], af[mt][1], af[mt][2], af[mt][3],
                              bf[nt][0], bf[nt][1]);
        }
        __syncthreads();
    }

    // Fused epilogue: route each column pair to Q / K / V-transposed fp16.
    uint32_t* Qh32 = (uint32_t*)g_Qh;
    uint32_t* Kh32 = (uint32_t*)g_Kh;
    #pragma unroll
    for (int mt = 0; mt < 4; mt++) {
        const int r = m0 + wr * 64 + mt * 16 + g;
        #pragma unroll
        for (int nt = 0; nt < 4; nt++) {
            const int c = n0 + wc * 32 + nt * 8 + 2 * t4;
            const float b0 = bias[c], b1 = bias[c + 1];
            const int h  = c / 144;
            const int rr = c - h * 144;
            float v00 = acc[mt][nt][0] + b0, v01 = acc[mt][nt][1] + b1;
            float v10 = acc[mt][nt][2] + b0, v11 = acc[mt][nt][3] + b1;
            if (rr < 48) {
                Qh32[((long)r * DIMV + h * PH + rr) >> 1] =
                    pkh2(v00 * SCALE, v01 * SCALE);
                Qh32[((long)(r + 8) * DIMV + h * PH + rr) >> 1] =
                    pkh2(v10 * SCALE, v11 * SCALE);
            } else if (rr < 96) {
                const int d = rr - 48;
                Kh32[((long)r * DIMV + h * PH + d) >> 1] = pkh2(v00, v01);
                Kh32[((long)(r + 8) * DIMV + h * PH + d) >> 1] = pkh2(v10, v11);
            } else {
                const int d = rr - 96;
                const int bb = r >> 11;
                const int t  = r & 2047;
                const long vb = ((long)(bb * NHEAD + h) * PH + d) * TSEQ + t;
                g_Vth[vb]            = __float2half_rn(v00);
                g_Vth[vb + TSEQ]     = __float2half_rn(v01);
                g_Vth[vb + 8]        = __float2half_rn(v10);
                g_Vth[vb + TSEQ + 8] = __float2half_rn(v11);
            }
        }
    }
}

// ---------------------------------------------------------------------------
// Generic tensor-core GEMM fp16 (R15 config: BK=32, 2-stage): out-projection.
// ---------------------------------------------------------------------------
__global__ void __launch_bounds__(256, 2) gemm_tc_kernel(
    const uint4* __restrict__ A, const uint4* __restrict__ B,
    const float* __restrict__ bias, float* __restrict__ C,
    int M, int N, int K)
{
    __shared__ __align__(16) __half sA[2][128][40];
    __shared__ __align__(16) __half sB[2][128][40];

    const int tid = threadIdx.x;
    const int wid = tid >> 5;
    const int lane = tid & 31;
    const int g = lane >> 2;
    const int t4 = lane & 3;
    const int wr = wid >> 2;
    const int wc = wid & 3;

    const int m0 = blockIdx.y * 128;
    const int n0 = blockIdx.x * 128;
    const int row = tid >> 1;
    const int half = tid & 1;
    const int Ku4 = K >> 3;

    const uint4* pA = A + (long)(m0 + row) * Ku4 + half * 2;
    const uint4* pB = B + (long)(n0 + row) * Ku4 + half * 2;

    const uint32_t dA0 = smem_u32(&sA[0][row][half * 16]);
    const uint32_t dB0 = smem_u32(&sB[0][row][half * 16]);
    const uint32_t stg = 128 * 40 * 2;

    float acc[4][4][4];
    #pragma unroll
    for (int mt = 0; mt < 4; mt++)
        #pragma unroll
        for (int nt = 0; nt < 4; nt++)
            #pragma unroll
            for (int j = 0; j < 4; j++) acc[mt][nt][j] = 0.f;

    const int NIT = K / 32;
    cpa16(dA0, pA);      cpa16(dA0 + 16, pA + 1);
    cpa16(dB0, pB);      cpa16(dB0 + 16, pB + 1);
    cpa_commit();

    for (int it = 0; it < NIT; it++) {
        if (it + 1 < NIT) {
            uint32_t s = (it + 1) & 1;
            const uint4* nA = pA + (it + 1) * 4;
            const uint4* nB = pB + (it + 1) * 4;
            cpa16(dA0 + s * stg, nA);      cpa16(dA0 + s * stg + 16, nA + 1);
            cpa16(dB0 + s * stg, nB);      cpa16(dB0 + s * stg + 16, nB + 1);
            cpa_commit();
            cpa_wait1();
        } else {
            cpa_wait0();
        }
        __syncthreads();

        const int st = it & 1;
        const uint32_t* sA0 = (const uint32_t*)sA[st];
        const uint32_t* sB0 = (const uint32_t*)sB[st];

        #pragma unroll
        for (int kk = 0; kk < 2; kk++) {
            const int ko = kk * 8;
            uint32_t bf[4][2];
            #pragma unroll
            for (int nt = 0; nt < 4; nt++) {
                int n = wc * 32 + nt * 8 + g;
                bf[nt][0] = sB0[n * 20 + ko + t4];
                bf[nt][1] = sB0[n * 20 + ko + t4 + 4];
            }
            uint32_t af[4][4];
            #pragma unroll
            for (int mt = 0; mt < 4; mt++) {
                int r0 = (wr * 64 + mt * 16 + g) * 20 + ko;
                int r1 = r0 + 8 * 20;
                af[mt][0] = sA0[r0 + t4];     af[mt][1] = sA0[r1 + t4];
                af[mt][2] = sA0[r0 + t4 + 4]; af[mt][3] = sA0[r1 + t4 + 4];
            }
            #pragma unroll
            for (int mt = 0; mt < 4; mt++)
                #pragma unroll
                for (int nt = 0; nt < 4; nt++)
                    mma16816h(acc[mt][nt], af[mt][0], af[mt][1], af[mt][2], af[mt][3],
                              bf[nt][0], bf[nt][1]);
        }
        __syncthreads();
    }

    #pragma unroll
    for (int mt = 0; mt < 4; mt++) {
        int r = m0 + wr * 64 + mt * 16 + g;
        #pragma unroll
        for (int nt = 0; nt < 4; nt++) {
            int c = n0 + wc * 32 + nt * 8 + 2 * t4;
            float b0 = bias[c], b1 = bias[c + 1];
            *(float2*)&C[(long)r * N + c] =
                make_float2(acc[mt][nt][0] + b0, acc[mt][nt][1] + b1);
            *(float2*)&C[(long)(r + 8) * N + c] =
                make_float2(acc[mt][nt][2] + b0, acc[mt][nt][3] + b1);
        }
    }
}

// ---------------------------------------------------------------------------
// Flash attention fp16 (R15 config: 2-stage, two syncs/tile).
// ---------------------------------------------------------------------------
#define SK_ELEMS (64 * 56)                 // 3584
#define STAGE_ELEMS (SK_ELEMS + 48 * 72)   // 7040
#define ATTN_SMEM (2 * STAGE_ELEMS * 2)    // 28160 bytes

__global__ void __launch_bounds__(256, 2) attn_mma_kernel()
{
    extern __shared__ __align__(16) __half dyn[];

    const int tid = threadIdx.x;
    const int wid = tid >> 5;
    const int lane = tid & 31;
    const int g = lane >> 2;
    const int t4 = lane & 3;

    const int bh = blockIdx.y;
    const int b = bh >> 4;
    const int h = bh & 15;
    const int qr0 = blockIdx.x * 128 + wid * 16;
    const long rowg  = (long)b * TSEQ + qr0 + g;
    const long rowg8 = rowg + 8;

    auto load_tile = [&](int kb, int st) {
        __half* base = dyn + st * STAGE_ELEMS;
        #pragma unroll
        for (int i = 0; i < 3; i++) {
            int idx = tid + 256 * i;
            if (idx < 384) {                     // K: 64 rows x 6 chunks
                int key = idx / 6, c = idx - key * 6;
                const __half* src = g_Kh
                    + (long)(b * TSEQ + kb + key) * DIMV + h * PH + c * 8;
                cpa16(smem_u32(base + key * 56 + c * 8), src);
            } else {                             // V: 48 dims x 8 chunks
                int v = idx - 384;
                int d = v >> 3, c = v & 7;
                const __half* src = g_Vth
                    + (long)bh * (PH * TSEQ) + d * TSEQ + kb + c * 8;
                cpa16(smem_u32(base + SK_ELEMS + d * 72 + c * 8), src);
            }
        }
        cpa_commit();
    };

    const uint32_t* Qh32 = (const uint32_t*)g_Qh;
    uint32_t qh[3][4];
    #pragma unroll
    for (int kk = 0; kk < 3; kk++) {
        long o0 = rowg  * 384 + h * 24 + kk * 8 + t4;
        long o1 = rowg8 * 384 + h * 24 + kk * 8 + t4;
        qh[kk][0] = Qh32[o0];     qh[kk][1] = Qh32[o1];
        qh[kk][2] = Qh32[o0 + 4]; qh[kk][3] = Qh32[o1 + 4];
    }

    float O[6][4];
    #pragma unroll
    for (int i = 0; i < 6; i++)
        #pragma unroll
        for (int j = 0; j < 4; j++) O[i][j] = 0.f;
    float m0 = -1e30f, m1 = -1e30f, l0 = 0.f, l1 = 0.f;

    load_tile(0, 0);

    const int NT = TSEQ / 64;
    for (int t = 0; t < NT; t++) {
        if (t + 1 < NT) {
            load_tile((t + 1) * 64, (t + 1) & 1);
            cpa_wait1();
        } else {
            cpa_wait0();
        }
        __syncthreads();

        const int st = t & 1;
        const __half* sK0 = dyn + st * STAGE_ELEMS;
        const __half* sV0 = sK0 + SK_ELEMS;

        float S[8][4];
        #pragma unroll
        for (int n = 0; n < 8; n++)
            #pragma unroll
            for (int j = 0; j < 4; j++) S[n][j] = 0.f;

        #pragma unroll
        for (int kk = 0; kk < 3; kk++) {
            uint32_t kf[8][2];
            #pragma unroll
            for (int n = 0; n < 8; n++) {
                const uint32_t* kp = (const uint32_t*)(sK0 + (n * 8 + g) * 56 + kk * 16 + 2 * t4);
                kf[n][0] = kp[0]; kf[n][1] = kp[4];
            }
            #pragma unroll
            for (int n = 0; n < 8; n++)
                mma16816h(S[n], qh[kk][0], qh[kk][1], qh[kk][2], qh[kk][3], kf[n][0], kf[n][1]);
        }

        float rmax0 = -1e30f, rmax1 = -1e30f;
        #pragma unroll
        for (int n = 0; n < 8; n++) {
            rmax0 = fmaxf(rmax0, fmaxf(S[n][0], S[n][1]));
            rmax1 = fmaxf(rmax1, fmaxf(S[n][2], S[n][3]));
        }
        rmax0 = fmaxf(rmax0, __shfl_xor_sync(0xffffffffu, rmax0, 1));
        rmax0 = fmaxf(rmax0, __shfl_xor_sync(0xffffffffu, rmax0, 2));
        rmax1 = fmaxf(rmax1, __shfl_xor_sync(0xffffffffu, rmax1, 1));
        rmax1 = fmaxf(rmax1, __shfl_xor_sync(0xffffffffu, rmax1, 2));

        float mn0 = fmaxf(m0, rmax0);
        float mn1 = fmaxf(m1, rmax1);
        float corr0 = __expf(m0 - mn0);
        float corr1 = __expf(m1 - mn1);
        m0 = mn0; m1 = mn1;
        l0 *= corr0; l1 *= corr1;
        #pragma unroll
        for (int nd = 0; nd < 6; nd++) {
            O[nd][0] *= corr0; O[nd][1] *= corr0;
            O[nd][2] *= corr1; O[nd][3] *= corr1;
        }

        float ps0 = 0.f, ps1 = 0.f;
        #pragma unroll
        for (int n = 0; n < 8; n++) {
            S[n][0] = __expf(S[n][0] - m0);
            S[n][1] = __expf(S[n][1] - m0);
            S[n][2] = __expf(S[n][2] - m1);
            S[n][3] = __expf(S[n][3] - m1);
            ps0 += S[n][0] + S[n][1];
            ps1 += S[n][2] + S[n][3];
        }
        ps0 += __shfl_xor_sync(0xffffffffu, ps0, 1);
        ps0 += __shfl_xor_sync(0xffffffffu, ps0, 2);
        ps1 += __shfl_xor_sync(0xffffffffu, ps1, 1);
        ps1 += __shfl_xor_sync(0xffffffffu, ps1, 2);
        l0 += ps0; l1 += ps1;

        #pragma unroll
        for (int kk = 0; kk < 4; kk++) {
            uint32_t ph[4];
            #pragma unroll
            for (int half = 0; half < 2; half++) {
                const float* Sc = S[2 * kk + half];
                ph[2 * half + 0] = pkh2(Sc[0], Sc[1]);
                ph[2 * half + 1] = pkh2(Sc[2], Sc[3]);
            }
            uint32_t vf[6][2];
            #pragma unroll
            for (int nd = 0; nd < 6; nd++) {
                const uint32_t* vp = (const uint32_t*)(sV0 + (nd * 8 + g) * 72 + kk * 16 + 2 * t4);
                vf[nd][0] = vp[0]; vf[nd][1] = vp[4];
            }
            #pragma unroll
            for (int nd = 0; nd < 6; nd++)
                mma16816h(O[nd], ph[0], ph[1], ph[2], ph[3], vf[nd][0], vf[nd][1]);
        }
        __syncthreads();
    }

    const float invl0 = 1.0f / l0;
    const float invl1 = 1.0f / l1;
    #pragma unroll
    for (int nd = 0; nd < 6; nd++) {
        long c = h * PH + nd * 8 + 2 * t4;
        g_AttH[(rowg  * DIMV + c) >> 1] =
            pkh2(O[nd][0] * invl0, O[nd][1] * invl0);
        g_AttH[(rowg8 * DIMV + c) >> 1] =
            pkh2(O[nd][2] * invl1, O[nd][3] * invl1);
    }
}

// ---------------------------------------------------------------------------
extern "C" void kernel_launch(void* const* d_in, const int* in_sizes, int n_in,
                              void* d_out, int out_size)
{
    const float* x     = (const float*)d_in[0];
    const float* w_in  = (const float*)d_in[1];
    const float* b_in  = (const float*)d_in[2];
    const float* w_out = (const float*)d_in[3];
    const float* b_out = (const float*)d_in[4];
    float* out = (float*)d_out;

    uint32_t *Xh, *WinTh, *WoutTh, *AttH;
    cudaGetSymbolAddress((void**)&Xh, g_Xh);
    cudaGetSymbolAddress((void**)&WinTh, g_WinTh);
    cudaGetSymbolAddress((void**)&WoutTh, g_WoutTh);
    cudaGetSymbolAddress((void**)&AttH, g_AttH);

    // 1) merged converts: x + w_in^T + w_out^T in one launch
    convert_all_kernel<<<XB + WIB + WOB, 256>>>(x, w_in, w_out);

    // 2) QKV projection with fused fp16 Q/K/V-transpose epilogue
    {
        dim3 grid(NQKV / 128, MTOT / 128);
        gemm_qkv_fused_kernel<<<grid, 256>>>((const uint4*)Xh,
                                             (const uint4*)WinTh, b_in);
    }

    // 3) Attention (QK x1, PV x1)
    {
        dim3 grid(TSEQ / 128, 64);
        attn_mma_kernel<<<grid, 256, ATTN_SMEM>>>();
    }

    // 4) Output projection -> fp32 d_out
    {
        dim3 grid(DIMV / 128, MTOT / 128);
        gemm_tc_kernel<<<grid, 256>>>((const uint4*)AttH, (const uint4*)WoutTh,
                                      b_out, out, MTOT, DIMV, DIMV);
    }
}